// round 14
// baseline (speedup 1.0000x reference)
#include <cuda_runtime.h>
#include <cuda_fp16.h>
#include <cstdint>

// Shape: x [B=4, S=2048, D=1024] fp32; Wq/Wk/Wv [D, D] fp32 (y = x @ W.T)
#define BATCH 4
#define SEQ   2048
#define DM    1024
#define MTOT  (BATCH * SEQ)   // 8192

__device__ __half g_X[MTOT * DM];
__device__ __half g_W[3 * DM * DM];
__device__ __half g_Q[MTOT * DM];
__device__ __half g_K[MTOT * DM];
__device__ __half g_V[MTOT * DM];
__device__ __half g_Ph[(long)MTOT * SEQ];   // fp16 unnormalized exp(scores/32)
__device__ float  g_S[MTOT];                // fp32 row sums of g_Ph

// ---------------------------------------------------------------------------
// FP16 mma.sync (m16n8k16) GEMM, cp.async 3-stage, BK=64 halves.
// Block tile 128x128, 4 warps (128 threads) 2x2, warp tile 64x64.
// EPI: 0 = plain half stores (qkv)
//      1 = exp(scale*acc) half stores + atomicAdd row sums into g_S (scores)
//      2 = float stores divided by g_S[row] (out)
// ---------------------------------------------------------------------------
#define BM 128
#define BN 128
#define TBK 64
#define NTHR 128
#define STAGES 3
#define A_STAGE 16384
#define B_STAGE 16384
#define STAGE   (A_STAGE + B_STAGE)
#define DYN_BYTES (STAGES * STAGE + 256)

__device__ __forceinline__ uint32_t smem_u32(const void* p) {
    uint32_t a;
    asm("{ .reg .u64 t; cvta.to.shared.u64 t, %1; cvt.u32.u64 %0, t; }" : "=r"(a) : "l"(p));
    return a;
}
__device__ __forceinline__ void mma_f16(
    float c[4], uint32_t a0, uint32_t a1, uint32_t a2, uint32_t a3,
    uint32_t b0, uint32_t b1)
{
    asm volatile(
        "mma.sync.aligned.m16n8k16.row.col.f32.f16.f16.f32 "
        "{%0,%1,%2,%3}, {%4,%5,%6,%7}, {%8,%9}, {%0,%1,%2,%3};"
        : "+f"(c[0]), "+f"(c[1]), "+f"(c[2]), "+f"(c[3])
        : "r"(a0), "r"(a1), "r"(a2), "r"(a3), "r"(b0), "r"(b1));
}
__device__ __forceinline__ void ldsm_x4(
    uint32_t& r0, uint32_t& r1, uint32_t& r2, uint32_t& r3, uint32_t addr)
{
    asm volatile("ldmatrix.sync.aligned.m8n8.x4.shared.b16 {%0,%1,%2,%3}, [%4];"
                 : "=r"(r0), "=r"(r1), "=r"(r2), "=r"(r3) : "r"(addr));
}
__device__ __forceinline__ void ldsm_x4_t(
    uint32_t& r0, uint32_t& r1, uint32_t& r2, uint32_t& r3, uint32_t addr)
{
    asm volatile("ldmatrix.sync.aligned.m8n8.x4.trans.shared.b16 {%0,%1,%2,%3}, [%4];"
                 : "=r"(r0), "=r"(r1), "=r"(r2), "=r"(r3) : "r"(addr));
}
__device__ __forceinline__ void cp16(uint32_t dst, const void* src) {
    asm volatile("cp.async.cg.shared.global [%0], [%1], 16;" :: "r"(dst), "l"(src));
}
#define CP_COMMIT() asm volatile("cp.async.commit_group;" ::: "memory")
#define CP_WAIT1()  asm volatile("cp.async.wait_group 1;" ::: "memory")

// B_NK = true : C[m][n] = sum_k A[m][k] * B[n][k]   (B [N,K] half)
// B_NK = false: C[m][n] = sum_k A[m][k] * B[k][n]   (B [K,N] half)
template <bool B_NK, int EPI, typename OutT>
__device__ __forceinline__ void gemm_body(
    const __half* __restrict__ A, long lda,
    const __half* __restrict__ B, long ldb,
    OutT* __restrict__ C, long ldc, int K, long srow0)
{
    extern __shared__ char dynsm[];
    const uint32_t sraw = smem_u32(dynsm);
    const uint32_t sb   = (sraw + 127) & ~127u;

    const int t = threadIdx.x, lane = t & 31, warp = t >> 5;
    const int m0 = blockIdx.y * BM, n0 = blockIdx.x * BN;
    const int wm = (warp >> 1) * 64, wn = (warp & 1) * 64;
    const int fr = lane >> 2, fc = lane & 3;

    auto load_stage = [&](int slot, int k0) {
        const uint32_t ab = sb + slot * STAGE;
        const uint32_t bb = ab + A_STAGE;
#pragma unroll
        for (int it = 0; it < 8; it++) {
            int idx = t + it * NTHR;
            int row = idx >> 3, c = idx & 7;
            cp16(ab + row * 128 + ((c ^ (row & 7)) << 4),
                 A + (long)(m0 + row) * lda + k0 + c * 8);
        }
        if (B_NK) {
#pragma unroll
            for (int it = 0; it < 8; it++) {
                int idx = t + it * NTHR;
                int row = idx >> 3, c = idx & 7;
                cp16(bb + row * 128 + ((c ^ (row & 7)) << 4),
                     B + (long)(n0 + row) * ldb + k0 + c * 8);
            }
        } else {
#pragma unroll
            for (int it = 0; it < 8; it++) {
                int idx = t + it * NTHR;
                int k = idx >> 4, c = idx & 15;
                cp16(bb + k * 256 + ((c ^ (k & 7)) << 4),
                     B + (long)(k0 + k) * ldb + n0 + c * 8);
            }
        }
    };

    float acc[4][8][4];
#pragma unroll
    for (int i = 0; i < 4; i++)
#pragma unroll
        for (int j = 0; j < 8; j++)
#pragma unroll
            for (int r = 0; r < 4; r++) acc[i][j][r] = 0.f;

    const int x7    = lane & 7;
    const int a_row = wm + ((lane >> 3) & 1) * 8 + x7;
    const int a_kc  = (lane >> 4) & 1;
    const int b_row = wn + ((lane >> 4) & 1) * 8 + x7;   // B_NK
    const int b_kc  = (lane >> 3) & 1;
    const int v_krow = ((lane >> 3) & 1) * 8 + x7;       // B_KN
    const int v_cof  = (lane >> 4) & 1;

    const int nT = K / TBK;
    load_stage(0, 0);   CP_COMMIT();
    load_stage(1, TBK); CP_COMMIT();

    for (int ti = 0; ti < nT; ti++) {
        CP_WAIT1();
        __syncthreads();

        const int pf = ti + 2;
        if (pf < nT) load_stage(pf % STAGES, pf * TBK);
        CP_COMMIT();

        const int slot = ti % STAGES;
        const uint32_t ab = sb + slot * STAGE;
        const uint32_t bb = ab + A_STAGE;

#pragma unroll
        for (int ks = 0; ks < 4; ks++) {      // 4 x K=16 per BK=64
            uint32_t af[4][4], bf[8][2];
#pragma unroll
            for (int im = 0; im < 4; im++) {
                uint32_t addr = ab + (a_row + im * 16) * 128 +
                                (((ks * 2 + a_kc) ^ x7) << 4);
                ldsm_x4(af[im][0], af[im][1], af[im][2], af[im][3], addr);
            }
            if (B_NK) {
#pragma unroll
                for (int p = 0; p < 4; p++) {
                    uint32_t addr = bb + (b_row + p * 16) * 128 +
                                    (((ks * 2 + b_kc) ^ x7) << 4);
                    ldsm_x4(bf[2 * p][0], bf[2 * p][1],
                            bf[2 * p + 1][0], bf[2 * p + 1][1], addr);
                }
            } else {
#pragma unroll
                for (int p = 0; p < 4; p++) {
                    int row_k = ks * 16 + v_krow;
                    int chunk = (wn >> 3) + 2 * p + v_cof;
                    uint32_t addr = bb + row_k * 256 + ((chunk ^ x7) << 4);
                    ldsm_x4_t(bf[2 * p][0], bf[2 * p][1],
                              bf[2 * p + 1][0], bf[2 * p + 1][1], addr);
                }
            }
#pragma unroll
            for (int im = 0; im < 4; im++)
#pragma unroll
                for (int in = 0; in < 8; in++)
                    mma_f16(acc[im][in], af[im][0], af[im][1], af[im][2], af[im][3],
                            bf[in][0], bf[in][1]);
        }
    }

    const float S = 0.03125f;   // 1/sqrt(1024)
#pragma unroll
    for (int im = 0; im < 4; im++) {
        long row = m0 + wm + im * 16 + fr;
        float s0 = 0.f, s1 = 0.f;     // EPI==1 row sums (rounded values)
        float i0 = 1.f, i1 = 1.f;     // EPI==2 inverse row sums
        if (EPI == 2) {
            i0 = 1.0f / g_S[srow0 + row];
            i1 = 1.0f / g_S[srow0 + row + 8];
        }
#pragma unroll
        for (int in = 0; in < 8; in++) {
            long col = n0 + wn + in * 8 + 2 * fc;
            if (EPI == 0) {
                *(__half2*)((__half*)C + row * ldc + col) =
                    __floats2half2_rn(acc[im][in][0], acc[im][in][1]);
                *(__half2*)((__half*)C + (row + 8) * ldc + col) =
                    __floats2half2_rn(acc[im][in][2], acc[im][in][3]);
            } else if (EPI == 1) {
                __half2 h0 = __floats2half2_rn(__expf(acc[im][in][0] * S),
                                               __expf(acc[im][in][1] * S));
                __half2 h1 = __floats2half2_rn(__expf(acc[im][in][2] * S),
                                               __expf(acc[im][in][3] * S));
                *(__half2*)((__half*)C + row * ldc + col)       = h0;
                *(__half2*)((__half*)C + (row + 8) * ldc + col) = h1;
                s0 += __low2float(h0) + __high2float(h0);
                s1 += __low2float(h1) + __high2float(h1);
            } else {
                *(float2*)((float*)C + row * ldc + col) =
                    make_float2(acc[im][in][0] * i0, acc[im][in][1] * i0);
                *(float2*)((float*)C + (row + 8) * ldc + col) =
                    make_float2(acc[im][in][2] * i1, acc[im][in][3] * i1);
            }
        }
        if (EPI == 1) {
            atomicAdd(&g_S[srow0 + row],     s0);
            atomicAdd(&g_S[srow0 + row + 8], s1);
        }
    }
}

// ---------------------------------------------------------------------------
__global__ __launch_bounds__(256) void round_all_kernel(
    const float* __restrict__ x,  const float* __restrict__ Wq,
    const float* __restrict__ Wk, const float* __restrict__ Wv)
{
    const long i = ((long)blockIdx.x * 256 + threadIdx.x) * 8;
    const long NX = (long)MTOT * DM;
    const long NW = (long)DM * DM;
    const float* src; __half* dst; long off;
    if (i < NX)               { src = x;  dst = g_X;          off = i; }
    else if (i < NX + NW)     { src = Wq; dst = g_W;          off = i - NX; }
    else if (i < NX + 2 * NW) { src = Wk; dst = g_W + NW;     off = i - NX - NW; }
    else                      { src = Wv; dst = g_W + 2 * NW; off = i - NX - 2 * NW; }
    float4 v0 = *(const float4*)(src + off);
    float4 v1 = *(const float4*)(src + off + 4);
    __half2 h0 = __floats2half2_rn(v0.x, v0.y);
    __half2 h1 = __floats2half2_rn(v0.z, v0.w);
    __half2 h2 = __floats2half2_rn(v1.x, v1.y);
    __half2 h3 = __floats2half2_rn(v1.z, v1.w);
    uint4 u;
    u.x = *(uint32_t*)&h0; u.y = *(uint32_t*)&h1;
    u.z = *(uint32_t*)&h2; u.w = *(uint32_t*)&h3;
    *(uint4*)(dst + off) = u;
}

__global__ __launch_bounds__(256) void zero_s_kernel()
{
    g_S[blockIdx.x * 256 + threadIdx.x] = 0.f;
}

__global__ __launch_bounds__(NTHR, 2) void qkv_kernel()
{
    const __half* W = g_W + (long)blockIdx.z * DM * DM;
    __half* C = (blockIdx.z == 0) ? g_Q : (blockIdx.z == 1) ? g_K : g_V;
    gemm_body<true, 0, __half>(g_X, DM, W, DM, C, DM, DM, 0);
}

// scores + fused softmax numerator: writes exp(QK^T/32) fp16 + row sums.
__global__ __launch_bounds__(NTHR, 2) void scores_kernel()
{
    const long b = blockIdx.z;
    gemm_body<true, 1, __half>(g_Q + b * (long)SEQ * DM, DM,
                               g_K + b * (long)SEQ * DM, DM,
                               g_Ph + b * (long)SEQ * SEQ, SEQ, DM, b * SEQ);
}

// out = (e @ V) / g_S[row]
__global__ __launch_bounds__(NTHR, 2) void out_kernel(float* __restrict__ out)
{
    const long b = blockIdx.z;
    gemm_body<false, 2, float>(g_Ph + b * (long)SEQ * SEQ, SEQ,
                               g_V + b * (long)SEQ * DM, DM,
                               out + b * (long)SEQ * DM, DM, SEQ, b * SEQ);
}

// ---------------------------------------------------------------------------
extern "C" void kernel_launch(void* const* d_in, const int* in_sizes, int n_in,
                              void* d_out, int out_size)
{
    const float* x  = (const float*)d_in[0];
    const float* Wq = (const float*)d_in[1];
    const float* Wk = (const float*)d_in[2];
    const float* Wv = (const float*)d_in[3];
    float* out = (float*)d_out;

    static bool attr_done = false;
    if (!attr_done) {
        cudaFuncSetAttribute(qkv_kernel,    cudaFuncAttributeMaxDynamicSharedMemorySize, DYN_BYTES);
        cudaFuncSetAttribute(scores_kernel, cudaFuncAttributeMaxDynamicSharedMemorySize, DYN_BYTES);
        cudaFuncSetAttribute(out_kernel,    cudaFuncAttributeMaxDynamicSharedMemorySize, DYN_BYTES);
        attr_done = true;
    }

    dim3 blk(NTHR);
    const long totalElems = (long)MTOT * DM + 3L * DM * DM;
    round_all_kernel<<<(unsigned)(totalElems / 2048), 256>>>(x, Wq, Wk, Wv);
    zero_s_kernel<<<MTOT / 256, 256>>>();

    qkv_kernel   <<<dim3(DM / BN,  MTOT / BM, 3),     blk, DYN_BYTES>>>();
    scores_kernel<<<dim3(SEQ / BN, SEQ / BM,  BATCH), blk, DYN_BYTES>>>();
    out_kernel   <<<dim3(DM / BN,  SEQ / BM,  BATCH), blk, DYN_BYTES>>>(out);
}

// round 15
// speedup vs baseline: 1.0082x; 1.0082x over previous
#include <cuda_runtime.h>
#include <cuda_fp16.h>
#include <cstdint>

// Shape: x [B=4, S=2048, D=1024] fp32; Wq/Wk/Wv [D, D] fp32 (y = x @ W.T)
#define BATCH 4
#define SEQ   2048
#define DM    1024
#define MTOT  (BATCH * SEQ)   // 8192

__device__ __half g_X[MTOT * DM];
__device__ __half g_W[3 * DM * DM];
__device__ __half g_Q[MTOT * DM];
__device__ __half g_K[MTOT * DM];
__device__ __half g_V[MTOT * DM];
__device__ __half g_Ph[(long)MTOT * SEQ];   // fp16 unnormalized exp(scores/32)
__device__ float  g_S[MTOT];                // fp32 row sums of g_Ph

// ---------------------------------------------------------------------------
// FP16 mma.sync (m16n8k16) GEMM, cp.async 3-stage, BK=64 halves.
// Block tile 128x128, 4 warps (128 threads) 2x2, warp tile 64x64.
// EPI: 0 = plain half stores (qk / v)
//      1 = exp2(scale2*acc) half stores + atomicAdd row sums into g_S (scores)
//      2 = float stores divided by g_S[row] (out)
// ---------------------------------------------------------------------------
#define BM 128
#define BN 128
#define TBK 64
#define NTHR 128
#define STAGES 3
#define A_STAGE 16384
#define B_STAGE 16384
#define STAGE   (A_STAGE + B_STAGE)
#define DYN_BYTES (STAGES * STAGE + 256)

__device__ __forceinline__ uint32_t smem_u32(const void* p) {
    uint32_t a;
    asm("{ .reg .u64 t; cvta.to.shared.u64 t, %1; cvt.u32.u64 %0, t; }" : "=r"(a) : "l"(p));
    return a;
}
__device__ __forceinline__ void mma_f16(
    float c[4], uint32_t a0, uint32_t a1, uint32_t a2, uint32_t a3,
    uint32_t b0, uint32_t b1)
{
    asm volatile(
        "mma.sync.aligned.m16n8k16.row.col.f32.f16.f16.f32 "
        "{%0,%1,%2,%3}, {%4,%5,%6,%7}, {%8,%9}, {%0,%1,%2,%3};"
        : "+f"(c[0]), "+f"(c[1]), "+f"(c[2]), "+f"(c[3])
        : "r"(a0), "r"(a1), "r"(a2), "r"(a3), "r"(b0), "r"(b1));
}
__device__ __forceinline__ void ldsm_x4(
    uint32_t& r0, uint32_t& r1, uint32_t& r2, uint32_t& r3, uint32_t addr)
{
    asm volatile("ldmatrix.sync.aligned.m8n8.x4.shared.b16 {%0,%1,%2,%3}, [%4];"
                 : "=r"(r0), "=r"(r1), "=r"(r2), "=r"(r3) : "r"(addr));
}
__device__ __forceinline__ void ldsm_x4_t(
    uint32_t& r0, uint32_t& r1, uint32_t& r2, uint32_t& r3, uint32_t addr)
{
    asm volatile("ldmatrix.sync.aligned.m8n8.x4.trans.shared.b16 {%0,%1,%2,%3}, [%4];"
                 : "=r"(r0), "=r"(r1), "=r"(r2), "=r"(r3) : "r"(addr));
}
__device__ __forceinline__ void cp16(uint32_t dst, const void* src) {
    asm volatile("cp.async.cg.shared.global [%0], [%1], 16;" :: "r"(dst), "l"(src));
}
#define CP_COMMIT() asm volatile("cp.async.commit_group;" ::: "memory")
#define CP_WAIT1()  asm volatile("cp.async.wait_group 1;" ::: "memory")

// B_NK = true : C[m][n] = sum_k A[m][k] * B[n][k]   (B [N,K] half)
// B_NK = false: C[m][n] = sum_k A[m][k] * B[k][n]   (B [K,N] half)
template <bool B_NK, int EPI, typename OutT>
__device__ __forceinline__ void gemm_body(
    const __half* __restrict__ A, long lda,
    const __half* __restrict__ B, long ldb,
    OutT* __restrict__ C, long ldc, int K, long srow0)
{
    extern __shared__ char dynsm[];
    const uint32_t sraw = smem_u32(dynsm);
    const uint32_t sb   = (sraw + 127) & ~127u;

    const int t = threadIdx.x, lane = t & 31, warp = t >> 5;
    const int m0 = blockIdx.y * BM, n0 = blockIdx.x * BN;
    const int wm = (warp >> 1) * 64, wn = (warp & 1) * 64;
    const int fr = lane >> 2, fc = lane & 3;

    auto load_stage = [&](int slot, int k0) {
        const uint32_t ab = sb + slot * STAGE;
        const uint32_t bb = ab + A_STAGE;
#pragma unroll
        for (int it = 0; it < 8; it++) {
            int idx = t + it * NTHR;
            int row = idx >> 3, c = idx & 7;
            cp16(ab + row * 128 + ((c ^ (row & 7)) << 4),
                 A + (long)(m0 + row) * lda + k0 + c * 8);
        }
        if (B_NK) {
#pragma unroll
            for (int it = 0; it < 8; it++) {
                int idx = t + it * NTHR;
                int row = idx >> 3, c = idx & 7;
                cp16(bb + row * 128 + ((c ^ (row & 7)) << 4),
                     B + (long)(n0 + row) * ldb + k0 + c * 8);
            }
        } else {
#pragma unroll
            for (int it = 0; it < 8; it++) {
                int idx = t + it * NTHR;
                int k = idx >> 4, c = idx & 15;
                cp16(bb + k * 256 + ((c ^ (k & 7)) << 4),
                     B + (long)(k0 + k) * ldb + n0 + c * 8);
            }
        }
    };

    float acc[4][8][4];
#pragma unroll
    for (int i = 0; i < 4; i++)
#pragma unroll
        for (int j = 0; j < 8; j++)
#pragma unroll
            for (int r = 0; r < 4; r++) acc[i][j][r] = 0.f;

    const int x7    = lane & 7;
    const int a_row = wm + ((lane >> 3) & 1) * 8 + x7;
    const int a_kc  = (lane >> 4) & 1;
    const int b_row = wn + ((lane >> 4) & 1) * 8 + x7;   // B_NK
    const int b_kc  = (lane >> 3) & 1;
    const int v_krow = ((lane >> 3) & 1) * 8 + x7;       // B_KN
    const int v_cof  = (lane >> 4) & 1;

    const int nT = K / TBK;
    load_stage(0, 0);   CP_COMMIT();
    load_stage(1, TBK); CP_COMMIT();

    for (int ti = 0; ti < nT; ti++) {
        CP_WAIT1();
        __syncthreads();

        const int pf = ti + 2;
        if (pf < nT) load_stage(pf % STAGES, pf * TBK);
        CP_COMMIT();

        const int slot = ti % STAGES;
        const uint32_t ab = sb + slot * STAGE;
        const uint32_t bb = ab + A_STAGE;

#pragma unroll
        for (int ks = 0; ks < 4; ks++) {      // 4 x K=16 per BK=64
            uint32_t af[4][4], bf[8][2];
#pragma unroll
            for (int im = 0; im < 4; im++) {
                uint32_t addr = ab + (a_row + im * 16) * 128 +
                                (((ks * 2 + a_kc) ^ x7) << 4);
                ldsm_x4(af[im][0], af[im][1], af[im][2], af[im][3], addr);
            }
            if (B_NK) {
#pragma unroll
                for (int p = 0; p < 4; p++) {
                    uint32_t addr = bb + (b_row + p * 16) * 128 +
                                    (((ks * 2 + b_kc) ^ x7) << 4);
                    ldsm_x4(bf[2 * p][0], bf[2 * p][1],
                            bf[2 * p + 1][0], bf[2 * p + 1][1], addr);
                }
            } else {
#pragma unroll
                for (int p = 0; p < 4; p++) {
                    int row_k = ks * 16 + v_krow;
                    int chunk = (wn >> 3) + 2 * p + v_cof;
                    uint32_t addr = bb + row_k * 256 + ((chunk ^ x7) << 4);
                    ldsm_x4_t(bf[2 * p][0], bf[2 * p][1],
                              bf[2 * p + 1][0], bf[2 * p + 1][1], addr);
                }
            }
#pragma unroll
            for (int im = 0; im < 4; im++)
#pragma unroll
                for (int in = 0; in < 8; in++)
                    mma_f16(acc[im][in], af[im][0], af[im][1], af[im][2], af[im][3],
                            bf[in][0], bf[in][1]);
        }
    }

    const float S2 = 0.045084439f;   // (1/sqrt(1024)) * log2(e)
#pragma unroll
    for (int im = 0; im < 4; im++) {
        long row = m0 + wm + im * 16 + fr;
        float s0 = 0.f, s1 = 0.f;
        float i0 = 1.f, i1 = 1.f;
        if (EPI == 2) {
            i0 = 1.0f / g_S[srow0 + row];
            i1 = 1.0f / g_S[srow0 + row + 8];
        }
#pragma unroll
        for (int in = 0; in < 8; in++) {
            long col = n0 + wn + in * 8 + 2 * fc;
            if (EPI == 0) {
                *(__half2*)((__half*)C + row * ldc + col) =
                    __floats2half2_rn(acc[im][in][0], acc[im][in][1]);
                *(__half2*)((__half*)C + (row + 8) * ldc + col) =
                    __floats2half2_rn(acc[im][in][2], acc[im][in][3]);
            } else if (EPI == 1) {
                __half2 h0 = __floats2half2_rn(exp2f(acc[im][in][0] * S2),
                                               exp2f(acc[im][in][1] * S2));
                __half2 h1 = __floats2half2_rn(exp2f(acc[im][in][2] * S2),
                                               exp2f(acc[im][in][3] * S2));
                *(__half2*)((__half*)C + row * ldc + col)       = h0;
                *(__half2*)((__half*)C + (row + 8) * ldc + col) = h1;
                s0 += __low2float(h0) + __high2float(h0);
                s1 += __low2float(h1) + __high2float(h1);
            } else {
                *(float2*)((float*)C + row * ldc + col) =
                    make_float2(acc[im][in][0] * i0, acc[im][in][1] * i0);
                *(float2*)((float*)C + (row + 8) * ldc + col) =
                    make_float2(acc[im][in][2] * i1, acc[im][in][3] * i1);
            }
        }
        if (EPI == 1) {
            atomicAdd(&g_S[srow0 + row],     s0);
            atomicAdd(&g_S[srow0 + row + 8], s1);
        }
    }
}

// ---------------------------------------------------------------------------
// Rounding pass (x | Wq | Wk | Wv) + g_S zeroing folded in.
__global__ __launch_bounds__(256) void round_all_kernel(
    const float* __restrict__ x,  const float* __restrict__ Wq,
    const float* __restrict__ Wk, const float* __restrict__ Wv)
{
    const long j = (long)blockIdx.x * 256 + threadIdx.x;
    if (j < MTOT / 8) {
        float4 z = make_float4(0.f, 0.f, 0.f, 0.f);
        *(float4*)&g_S[j * 8]     = z;
        *(float4*)&g_S[j * 8 + 4] = z;
    }
    const long i = j * 8;
    const long NX = (long)MTOT * DM;
    const long NW = (long)DM * DM;
    const float* src; __half* dst; long off;
    if (i < NX)               { src = x;  dst = g_X;          off = i; }
    else if (i < NX + NW)     { src = Wq; dst = g_W;          off = i - NX; }
    else if (i < NX + 2 * NW) { src = Wk; dst = g_W + NW;     off = i - NX - NW; }
    else                      { src = Wv; dst = g_W + 2 * NW; off = i - NX - 2 * NW; }
    float4 v0 = *(const float4*)(src + off);
    float4 v1 = *(const float4*)(src + off + 4);
    __half2 h0 = __floats2half2_rn(v0.x, v0.y);
    __half2 h1 = __floats2half2_rn(v0.z, v0.w);
    __half2 h2 = __floats2half2_rn(v1.x, v1.y);
    __half2 h3 = __floats2half2_rn(v1.z, v1.w);
    uint4 u;
    u.x = *(uint32_t*)&h0; u.y = *(uint32_t*)&h1;
    u.z = *(uint32_t*)&h2; u.w = *(uint32_t*)&h3;
    *(uint4*)(dst + off) = u;
}

__global__ __launch_bounds__(NTHR, 2) void qk_kernel()
{
    const __half* W = g_W + (long)blockIdx.z * DM * DM;
    __half* C = (blockIdx.z == 0) ? g_Q : g_K;
    gemm_body<true, 0, __half>(g_X, DM, W, DM, C, DM, DM, 0);
}

__global__ __launch_bounds__(NTHR, 2) void v_kernel()
{
    gemm_body<true, 0, __half>(g_X, DM, g_W + 2L * DM * DM, DM, g_V, DM, DM, 0);
}

// scores + fused softmax numerator: writes exp(QK^T/32) fp16 + row sums.
__global__ __launch_bounds__(NTHR, 2) void scores_kernel()
{
    const long b = blockIdx.z;
    gemm_body<true, 1, __half>(g_Q + b * (long)SEQ * DM, DM,
                               g_K + b * (long)SEQ * DM, DM,
                               g_Ph + b * (long)SEQ * SEQ, SEQ, DM, b * SEQ);
}

// out = (e @ V) / g_S[row]
__global__ __launch_bounds__(NTHR, 2) void out_kernel(float* __restrict__ out)
{
    const long b = blockIdx.z;
    gemm_body<false, 2, float>(g_Ph + b * (long)SEQ * SEQ, SEQ,
                               g_V + b * (long)SEQ * DM, DM,
                               out + b * (long)SEQ * DM, DM, SEQ, b * SEQ);
}

// ---------------------------------------------------------------------------
extern "C" void kernel_launch(void* const* d_in, const int* in_sizes, int n_in,
                              void* d_out, int out_size)
{
    const float* x  = (const float*)d_in[0];
    const float* Wq = (const float*)d_in[1];
    const float* Wk = (const float*)d_in[2];
    const float* Wv = (const float*)d_in[3];
    float* out = (float*)d_out;

    static cudaStream_t s2 = nullptr;
    static cudaEvent_t  e0 = nullptr, e1 = nullptr;
    if (!s2) {
        cudaStreamCreateWithFlags(&s2, cudaStreamNonBlocking);
        cudaEventCreateWithFlags(&e0, cudaEventDisableTiming);
        cudaEventCreateWithFlags(&e1, cudaEventDisableTiming);
        cudaFuncSetAttribute(qk_kernel,     cudaFuncAttributeMaxDynamicSharedMemorySize, DYN_BYTES);
        cudaFuncSetAttribute(v_kernel,      cudaFuncAttributeMaxDynamicSharedMemorySize, DYN_BYTES);
        cudaFuncSetAttribute(scores_kernel, cudaFuncAttributeMaxDynamicSharedMemorySize, DYN_BYTES);
        cudaFuncSetAttribute(out_kernel,    cudaFuncAttributeMaxDynamicSharedMemorySize, DYN_BYTES);
    }

    dim3 blk(NTHR);
    const long totalElems = (long)MTOT * DM + 3L * DM * DM;
    round_all_kernel<<<(unsigned)(totalElems / 2048), 256>>>(x, Wq, Wk, Wv);

    // Fork: V projection runs on side stream, joined before out.
    cudaEventRecord(e0, 0);
    cudaStreamWaitEvent(s2, e0, 0);
    v_kernel<<<dim3(DM / BN, MTOT / BM), blk, DYN_BYTES, s2>>>();
    cudaEventRecord(e1, s2);

    qk_kernel    <<<dim3(DM / BN,  MTOT / BM, 2),     blk, DYN_BYTES>>>();
    scores_kernel<<<dim3(SEQ / BN, SEQ / BM,  BATCH), blk, DYN_BYTES>>>();
    cudaStreamWaitEvent(0, e1, 0);
    out_kernel   <<<dim3(DM / BN,  SEQ / BM,  BATCH), blk, DYN_BYTES>>>(out);
}